// round 7
// baseline (speedup 1.0000x reference)
#include <cuda_runtime.h>

// QuantumConv1d, 2-kernel pipeline (split kept deliberately: the 196.6MB writer
// needs max occupancy and must not inherit the conv tile's smem/reg footprint).
//  K1 (lean): warp0 folds circuit -> Q forms; quad-split conv + shfl reduce ->
//             expz -> g_ez (1.5MB, L2-resident), scalar-coalesced stores.
//  K2: writer: out[b,o,l] = W_post[o,:].ez[b,l,:] + b_post[o], float4 __stcs.

#define C_IN     80
#define L_IN     3000
#define OUT_CH   512
#define KW       3
#define TILE_L   128
#define THREADS  512
#define B_MAX    32
#define C_PER_G  (C_IN / 4)           // 20 channels per quad lane

__device__ float g_ez[B_MAX * L_IN * 4];   // expz per (b,l,q), 1.5 MB scratch

// ===================== Kernel 1: conv + inline Q + quadratic forms =====================
__global__ __launch_bounds__(THREADS)
void ez_kernel(const float* __restrict__ x,
               const float* __restrict__ W_pre,
               const float* __restrict__ b_pre,
               const float* __restrict__ qw)
{
    __shared__ float x_s[C_IN][TILE_L + 2];     // 41.6 KB
    __shared__ float w_s[C_IN * 12];            // [c][k][q] 3.75 KB
    __shared__ float Q_s[4][16];
    __shared__ float bpre_s[4];

    const int tid = threadIdx.x;
    const int b   = blockIdx.y;
    const int l0  = blockIdx.x * TILE_L;

    // ============ Phase 0: Q on warp 0 || staging on warps 1-15 ============
    if (tid < 32) {
        const int k = tid & 3;
        float sr[16], si[16];
        #pragma unroll
        for (int j = 0; j < 16; j++) { sr[j] = 0.f; si[j] = 0.f; }
        #pragma unroll
        for (int j = 0; j < 4; j++) if (j == k) sr[j] = 1.f;

        #pragma unroll
        for (int i = 0; i < 4; i++) {
            float phi = __ldg(qw + i * 3 + 0), th = __ldg(qw + i * 3 + 1), om = __ldg(qw + i * 3 + 2);
            float sh, ch; __sincosf(0.5f * th, &sh, &ch);
            float a = 0.5f * (phi + om), d = 0.5f * (phi - om);
            float sa, ca, sd, cd;
            __sincosf(a, &sa, &ca);
            __sincosf(d, &sd, &cd);
            float u00r =  ch * ca, u00i = -ch * sa;
            float u01r = -sh * cd, u01i = -sh * sd;
            float u10r =  sh * cd, u10i = -sh * sd;
            float u11r =  ch * ca, u11i =  ch * sa;
            const int s = 8 >> i;
            #pragma unroll
            for (int j = 0; j < 16; j++) {
                if ((j & s) == 0) {
                    const int j1 = j | s;
                    float ar = sr[j],  ai = si[j];
                    float br = sr[j1], bi = si[j1];
                    sr[j]  = u00r * ar - u00i * ai + u01r * br - u01i * bi;
                    si[j]  = u00r * ai + u00i * ar + u01r * bi + u01i * br;
                    sr[j1] = u10r * ar - u10i * ai + u11r * br - u11i * bi;
                    si[j1] = u10r * ai + u10i * ar + u11r * bi + u11i * br;
                }
            }
        }
        #define SWP(A,B) { float t; t=sr[A]; sr[A]=sr[B]; sr[B]=t; t=si[A]; si[A]=si[B]; si[B]=t; }
        SWP(8,12) SWP(9,13) SWP(10,14) SWP(11,15)   // cnot(0,1)
        SWP(4,6)  SWP(5,7)  SWP(12,14) SWP(13,15)   // cnot(1,2)
        SWP(2,3)  SWP(6,7)  SWP(10,11) SWP(14,15)   // cnot(2,3)
        #undef SWP

        float Qv[4][4];
        #pragma unroll
        for (int q = 0; q < 4; q++)
            #pragma unroll
            for (int m = 0; m < 4; m++) Qv[q][m] = 0.f;
        #pragma unroll
        for (int j = 0; j < 16; j++) {
            #pragma unroll
            for (int m = 0; m < 4; m++) {
                float arm = __shfl_sync(0xffffffffu, sr[j], m);
                float aim = __shfl_sync(0xffffffffu, si[j], m);
                float p = sr[j] * arm + si[j] * aim;
                Qv[0][m] += (j & 8) ? -p : p;
                Qv[1][m] += (j & 4) ? -p : p;
                Qv[2][m] += (j & 2) ? -p : p;
                Qv[3][m] += (j & 1) ? -p : p;
            }
        }
        if (tid < 4) {
            #pragma unroll
            for (int q = 0; q < 4; q++)
                #pragma unroll
                for (int m = 0; m < 4; m++)
                    Q_s[q][tid * 4 + m] = Qv[q][m];
            bpre_s[tid] = b_pre[tid];
        }
    } else {
        const int t = tid - 32;                     // 0..479
        for (int i = t; i < C_IN * 12; i += THREADS - 32) {
            int c = i / 12; int r = i - c * 12; int k = r >> 2; int q = r & 3;
            w_s[i] = W_pre[q * (C_IN * KW) + c * KW + k];
        }
        const float* xb = x + (size_t)b * C_IN * L_IN;
        for (int i = t; i < C_IN * (TILE_L + 2); i += THREADS - 32) {
            int c = i / (TILE_L + 2);
            int j = i - c * (TILE_L + 2);
            int l = l0 - 1 + j;
            x_s[c][j] = (l >= 0 && l < L_IN) ? xb[c * L_IN + l] : 0.0f;
        }
    }
    __syncthreads();

    // ============ Phase 1: quad-split conv + shfl reduce + one quadratic form ========
    const int pos = tid >> 2;                   // 0..127
    const int grp = tid & 3;                    // 0..3
    const int c0  = grp * C_PER_G;

    float v0 = 0.f, v1 = 0.f, v2 = 0.f, v3 = 0.f;
    #pragma unroll
    for (int ci = 0; ci < C_PER_G; ci++) {
        const int c = c0 + ci;
        float xa = x_s[c][pos], xb1 = x_s[c][pos + 1], xc = x_s[c][pos + 2];
        const float4* wr = (const float4*)&w_s[c * 12];
        float4 w0 = wr[0], w1 = wr[1], w2 = wr[2];
        v0 += w0.x * xa + w1.x * xb1 + w2.x * xc;
        v1 += w0.y * xa + w1.y * xb1 + w2.y * xc;
        v2 += w0.z * xa + w1.z * xb1 + w2.z * xc;
        v3 += w0.w * xa + w1.w * xb1 + w2.w * xc;
    }
    // quad reduction (lanes 4p..4p+3 hold partials for position p)
    v0 += __shfl_xor_sync(0xffffffffu, v0, 1);
    v1 += __shfl_xor_sync(0xffffffffu, v1, 1);
    v2 += __shfl_xor_sync(0xffffffffu, v2, 1);
    v3 += __shfl_xor_sync(0xffffffffu, v3, 1);
    v0 += __shfl_xor_sync(0xffffffffu, v0, 2);
    v1 += __shfl_xor_sync(0xffffffffu, v1, 2);
    v2 += __shfl_xor_sync(0xffffffffu, v2, 2);
    v3 += __shfl_xor_sync(0xffffffffu, v3, 2);

    v0 += bpre_s[0]; v1 += bpre_s[1]; v2 += bpre_s[2]; v3 += bpre_s[3];

    const int l = l0 + pos;
    if (l >= L_IN) return;

    const float inv = __frcp_rn(v0 * v0 + v1 * v1 + v2 * v2 + v3 * v3);
    const float* Qr = &Q_s[grp][0];
    float s;
    s  = v0 * (Qr[0]  * v0 + Qr[1]  * v1 + Qr[2]  * v2 + Qr[3]  * v3);
    s += v1 * (Qr[4]  * v0 + Qr[5]  * v1 + Qr[6]  * v2 + Qr[7]  * v3);
    s += v2 * (Qr[8]  * v0 + Qr[9]  * v1 + Qr[10] * v2 + Qr[11] * v3);
    s += v3 * (Qr[12] * v0 + Qr[13] * v1 + Qr[14] * v2 + Qr[15] * v3);

    // scalar coalesced store: consecutive tid -> consecutive floats
    g_ez[((size_t)b * L_IN + l) * 4 + grp] = s * inv;
}

// ===================== Kernel 2: broadcast + streaming stores (round-4, unchanged) ====
// grid: (24 l-tiles, 32 b). block = 512 (16 warps). Each warp sweeps o = wrp..511 step 16.
__global__ __launch_bounds__(512)
void write_kernel(const float* __restrict__ W_post,
                  const float* __restrict__ b_post,
                  float* __restrict__ out)
{
    const int tid  = threadIdx.x;
    const int b    = blockIdx.y;
    const int l0   = blockIdx.x * TILE_L;
    const int lane = tid & 31;
    const int wrp  = tid >> 5;                  // 0..15
    const int l4   = l0 + lane * 4;
    if (l4 >= L_IN) return;                     // L_IN % 4 == 0: no straddle

    const float4* ezp = (const float4*)&g_ez[((size_t)b * L_IN + l4) * 4];
    const float4 e0 = __ldg(ezp + 0);
    const float4 e1 = __ldg(ezp + 1);
    const float4 e2 = __ldg(ezp + 2);
    const float4 e3 = __ldg(ezp + 3);

    float* outb = out + (size_t)b * OUT_CH * L_IN;

    #pragma unroll 8
    for (int o = wrp; o < OUT_CH; o += 16) {
        const float4 wp = __ldg((const float4*)(W_post + o * 4));
        const float  bp = __ldg(b_post + o);
        float4 r;
        r.x = fmaf(wp.x, e0.x, fmaf(wp.y, e0.y, fmaf(wp.z, e0.z, fmaf(wp.w, e0.w, bp))));
        r.y = fmaf(wp.x, e1.x, fmaf(wp.y, e1.y, fmaf(wp.z, e1.z, fmaf(wp.w, e1.w, bp))));
        r.z = fmaf(wp.x, e2.x, fmaf(wp.y, e2.y, fmaf(wp.z, e2.z, fmaf(wp.w, e2.w, bp))));
        r.w = fmaf(wp.x, e3.x, fmaf(wp.y, e3.y, fmaf(wp.z, e3.z, fmaf(wp.w, e3.w, bp))));
        __stcs((float4*)(outb + (size_t)o * L_IN + l4), r);
    }
}

extern "C" void kernel_launch(void* const* d_in, const int* in_sizes, int n_in,
                              void* d_out, int out_size)
{
    const float* x      = (const float*)d_in[0];
    const float* W_pre  = (const float*)d_in[1];
    const float* b_pre  = (const float*)d_in[2];
    const float* W_post = (const float*)d_in[3];
    const float* b_post = (const float*)d_in[4];
    const float* qw     = (const float*)d_in[5];
    float* out = (float*)d_out;

    const int B = in_sizes[0] / (C_IN * L_IN);            // 32
    const int n_tiles = (L_IN + TILE_L - 1) / TILE_L;     // 24

    dim3 g1(n_tiles, B);
    ez_kernel<<<g1, THREADS>>>(x, W_pre, b_pre, qw);

    dim3 g2(n_tiles, B);
    write_kernel<<<g2, 512>>>(W_post, b_post, out);
}

// round 8
// speedup vs baseline: 1.0473x; 1.0473x over previous
#include <cuda_runtime.h>

// QuantumConv1d, 2-kernel pipeline.
//  K1 (ez): TILE=64, 256 thr, 1504 CTAs — latency-optimized: warp0 folds the
//           circuit into 4 quadratic forms Q_q while warps 1-7 stage the x tile;
//           quad-split conv + shfl reduce -> g_ez (1.5MB, L2-resident).
//  K2 (writer): 196.6MB float4 streaming stores; fine-grained units
//           (24 x 32 x 8 o-groups, 128 thr) to shrink the last-wave tail.

#define C_IN     80
#define L_IN     3000
#define OUT_CH   512
#define KW       3
#define EZTILE   64
#define EZTHR    256
#define WTILE    128
#define B_MAX    32
#define C_PER_G  (C_IN / 4)           // 20 channels per quad lane

__device__ float g_ez[B_MAX * L_IN * 4];   // expz per (b,l,q)

// ===================== Kernel 1: conv + inline Q + quadratic forms =====================
__global__ __launch_bounds__(EZTHR)
void ez_kernel(const float* __restrict__ x,
               const float* __restrict__ W_pre,
               const float* __restrict__ b_pre,
               const float* __restrict__ qw)
{
    __shared__ float x_s[C_IN][EZTILE + 2];     // 21.1 KB
    __shared__ float w_s[C_IN * 12];            // [c][k][q] 3.75 KB
    __shared__ float Q_s[4][16];
    __shared__ float bpre_s[4];

    const int tid = threadIdx.x;
    const int b   = blockIdx.y;
    const int l0  = blockIdx.x * EZTILE;

    // ============ Phase 0: Q on warp 0 || staging on warps 1-7 ============
    if (tid < 32) {
        const int k = tid & 3;
        float sr[16], si[16];
        #pragma unroll
        for (int j = 0; j < 16; j++) { sr[j] = 0.f; si[j] = 0.f; }
        #pragma unroll
        for (int j = 0; j < 4; j++) if (j == k) sr[j] = 1.f;

        #pragma unroll
        for (int i = 0; i < 4; i++) {
            float phi = __ldg(qw + i * 3 + 0), th = __ldg(qw + i * 3 + 1), om = __ldg(qw + i * 3 + 2);
            float sh, ch; __sincosf(0.5f * th, &sh, &ch);
            float a = 0.5f * (phi + om), d = 0.5f * (phi - om);
            float sa, ca, sd, cd;
            __sincosf(a, &sa, &ca);
            __sincosf(d, &sd, &cd);
            float u00r =  ch * ca, u00i = -ch * sa;
            float u01r = -sh * cd, u01i = -sh * sd;
            float u10r =  sh * cd, u10i = -sh * sd;
            float u11r =  ch * ca, u11i =  ch * sa;
            const int s = 8 >> i;
            #pragma unroll
            for (int j = 0; j < 16; j++) {
                if ((j & s) == 0) {
                    const int j1 = j | s;
                    float ar = sr[j],  ai = si[j];
                    float br = sr[j1], bi = si[j1];
                    sr[j]  = u00r * ar - u00i * ai + u01r * br - u01i * bi;
                    si[j]  = u00r * ai + u00i * ar + u01r * bi + u01i * br;
                    sr[j1] = u10r * ar - u10i * ai + u11r * br - u11i * bi;
                    si[j1] = u10r * ai + u10i * ar + u11r * bi + u11i * br;
                }
            }
        }
        #define SWP(A,B) { float t; t=sr[A]; sr[A]=sr[B]; sr[B]=t; t=si[A]; si[A]=si[B]; si[B]=t; }
        SWP(8,12) SWP(9,13) SWP(10,14) SWP(11,15)   // cnot(0,1)
        SWP(4,6)  SWP(5,7)  SWP(12,14) SWP(13,15)   // cnot(1,2)
        SWP(2,3)  SWP(6,7)  SWP(10,11) SWP(14,15)   // cnot(2,3)
        #undef SWP

        float Qv[4][4];
        #pragma unroll
        for (int q = 0; q < 4; q++)
            #pragma unroll
            for (int m = 0; m < 4; m++) Qv[q][m] = 0.f;
        #pragma unroll
        for (int j = 0; j < 16; j++) {
            #pragma unroll
            for (int m = 0; m < 4; m++) {
                float arm = __shfl_sync(0xffffffffu, sr[j], m);
                float aim = __shfl_sync(0xffffffffu, si[j], m);
                float p = sr[j] * arm + si[j] * aim;
                Qv[0][m] += (j & 8) ? -p : p;
                Qv[1][m] += (j & 4) ? -p : p;
                Qv[2][m] += (j & 2) ? -p : p;
                Qv[3][m] += (j & 1) ? -p : p;
            }
        }
        if (tid < 4) {
            #pragma unroll
            for (int q = 0; q < 4; q++)
                #pragma unroll
                for (int m = 0; m < 4; m++)
                    Q_s[q][tid * 4 + m] = Qv[q][m];
            bpre_s[tid] = b_pre[tid];
        }
    } else {
        const int t = tid - 32;                     // 0..223
        for (int i = t; i < C_IN * 12; i += EZTHR - 32) {
            int c = i / 12; int r = i - c * 12; int k = r >> 2; int q = r & 3;
            w_s[i] = W_pre[q * (C_IN * KW) + c * KW + k];
        }
        const float* xb = x + (size_t)b * C_IN * L_IN;
        for (int i = t; i < C_IN * (EZTILE + 2); i += EZTHR - 32) {
            int c = i / (EZTILE + 2);
            int j = i - c * (EZTILE + 2);
            int l = l0 - 1 + j;
            x_s[c][j] = (l >= 0 && l < L_IN) ? xb[c * L_IN + l] : 0.0f;
        }
    }
    __syncthreads();

    // ============ Phase 1: quad-split conv + shfl reduce + one quadratic form ========
    const int pos = tid >> 2;                   // 0..63
    const int grp = tid & 3;                    // 0..3
    const int c0  = grp * C_PER_G;

    float v0 = 0.f, v1 = 0.f, v2 = 0.f, v3 = 0.f;
    #pragma unroll
    for (int ci = 0; ci < C_PER_G; ci++) {
        const int c = c0 + ci;
        float xa = x_s[c][pos], xb1 = x_s[c][pos + 1], xc = x_s[c][pos + 2];
        const float4* wr = (const float4*)&w_s[c * 12];
        float4 w0 = wr[0], w1 = wr[1], w2 = wr[2];
        v0 += w0.x * xa + w1.x * xb1 + w2.x * xc;
        v1 += w0.y * xa + w1.y * xb1 + w2.y * xc;
        v2 += w0.z * xa + w1.z * xb1 + w2.z * xc;
        v3 += w0.w * xa + w1.w * xb1 + w2.w * xc;
    }
    v0 += __shfl_xor_sync(0xffffffffu, v0, 1);
    v1 += __shfl_xor_sync(0xffffffffu, v1, 1);
    v2 += __shfl_xor_sync(0xffffffffu, v2, 1);
    v3 += __shfl_xor_sync(0xffffffffu, v3, 1);
    v0 += __shfl_xor_sync(0xffffffffu, v0, 2);
    v1 += __shfl_xor_sync(0xffffffffu, v1, 2);
    v2 += __shfl_xor_sync(0xffffffffu, v2, 2);
    v3 += __shfl_xor_sync(0xffffffffu, v3, 2);

    v0 += bpre_s[0]; v1 += bpre_s[1]; v2 += bpre_s[2]; v3 += bpre_s[3];

    const int l = l0 + pos;
    if (l >= L_IN) return;

    const float inv = __frcp_rn(v0 * v0 + v1 * v1 + v2 * v2 + v3 * v3);
    const float* Qr = &Q_s[grp][0];
    float s;
    s  = v0 * (Qr[0]  * v0 + Qr[1]  * v1 + Qr[2]  * v2 + Qr[3]  * v3);
    s += v1 * (Qr[4]  * v0 + Qr[5]  * v1 + Qr[6]  * v2 + Qr[7]  * v3);
    s += v2 * (Qr[8]  * v0 + Qr[9]  * v1 + Qr[10] * v2 + Qr[11] * v3);
    s += v3 * (Qr[12] * v0 + Qr[13] * v1 + Qr[14] * v2 + Qr[15] * v3);

    g_ez[((size_t)b * L_IN + l) * 4 + grp] = s * inv;   // tid-consecutive -> coalesced
}

// ===================== Kernel 2: writer, fine-grained units =====================
// grid: (24 l-tiles, 32 b, 8 o-groups of 64). block = 128 (4 warps).
// Each warp sweeps 16 o's (o = og*64 + wrp, step 4); lane owns 4 contiguous l.
__global__ __launch_bounds__(128)
void write_kernel(const float* __restrict__ W_post,
                  const float* __restrict__ b_post,
                  float* __restrict__ out)
{
    const int tid  = threadIdx.x;
    const int b    = blockIdx.y;
    const int l0   = blockIdx.x * WTILE;
    const int og   = blockIdx.z;
    const int lane = tid & 31;
    const int wrp  = tid >> 5;                  // 0..3
    const int l4   = l0 + lane * 4;
    if (l4 >= L_IN) return;                     // L_IN % 4 == 0: no straddle

    const float4* ezp = (const float4*)&g_ez[((size_t)b * L_IN + l4) * 4];
    const float4 e0 = __ldg(ezp + 0);
    const float4 e1 = __ldg(ezp + 1);
    const float4 e2 = __ldg(ezp + 2);
    const float4 e3 = __ldg(ezp + 3);

    float* outb = out + (size_t)b * OUT_CH * L_IN + (size_t)og * 64 * L_IN;

    #pragma unroll 16
    for (int oi = 0; oi < 16; oi++) {
        const int o  = oi * 4 + wrp;                       // 0..63 within group
        const int oo = og * 64 + o;                        // global o
        const float4 wp = __ldg((const float4*)(W_post + oo * 4));
        const float  bp = __ldg(b_post + oo);
        float4 r;
        r.x = fmaf(wp.x, e0.x, fmaf(wp.y, e0.y, fmaf(wp.z, e0.z, fmaf(wp.w, e0.w, bp))));
        r.y = fmaf(wp.x, e1.x, fmaf(wp.y, e1.y, fmaf(wp.z, e1.z, fmaf(wp.w, e1.w, bp))));
        r.z = fmaf(wp.x, e2.x, fmaf(wp.y, e2.y, fmaf(wp.z, e2.z, fmaf(wp.w, e2.w, bp))));
        r.w = fmaf(wp.x, e3.x, fmaf(wp.y, e3.y, fmaf(wp.z, e3.z, fmaf(wp.w, e3.w, bp))));
        __stcs((float4*)(outb + (size_t)o * L_IN + l4), r);
    }
}

extern "C" void kernel_launch(void* const* d_in, const int* in_sizes, int n_in,
                              void* d_out, int out_size)
{
    const float* x      = (const float*)d_in[0];
    const float* W_pre  = (const float*)d_in[1];
    const float* b_pre  = (const float*)d_in[2];
    const float* W_post = (const float*)d_in[3];
    const float* b_post = (const float*)d_in[4];
    const float* qw     = (const float*)d_in[5];
    float* out = (float*)d_out;

    const int B = in_sizes[0] / (C_IN * L_IN);                  // 32
    const int ez_tiles = (L_IN + EZTILE - 1) / EZTILE;          // 47
    const int w_tiles  = (L_IN + WTILE - 1) / WTILE;            // 24

    dim3 g1(ez_tiles, B);
    ez_kernel<<<g1, EZTHR>>>(x, W_pre, b_pre, qw);

    dim3 g2(w_tiles, B, 8);
    write_kernel<<<g2, 128>>>(W_post, b_post, out);
}

// round 10
// speedup vs baseline: 1.0569x; 1.0091x over previous
#include <cuda_runtime.h>

// QuantumConv1d, 3-kernel pipeline:
//  K0 (1 warp, ~1us): fold circuit -> 4 quadratic forms Q_q (4x4), fully unrolled,
//      __sincosf + shfl. Isolated so its register footprint doesn't tax K1.
//  K1 (lean, ~40 regs): quad-split conv + shfl reduce + quadratic form -> g_ez.
//  K2 (writer, round-4 measured-best config): 196.6MB float4 streaming stores.

#define C_IN     80
#define L_IN     3000
#define OUT_CH   512
#define KW       3
#define EZTILE   64
#define EZTHR    256
#define WTILE    128
#define B_MAX    32
#define C_PER_G  (C_IN / 4)           // 20 channels per quad lane

__device__ float g_ez[B_MAX * L_IN * 4];   // expz per (b,l,q)
__device__ float g_Q[4][16];               // quadratic forms

// ===================== Kernel 0: Q fold (1 warp, fully unrolled) =====================
__global__ void setup_q(const float* __restrict__ qw)
{
    const int lane = threadIdx.x;
    const int k    = lane & 3;               // basis column this lane owns

    float sr[16], si[16];
    #pragma unroll
    for (int j = 0; j < 16; j++) { sr[j] = 0.f; si[j] = 0.f; }
    #pragma unroll
    for (int j = 0; j < 4; j++) if (j == k) sr[j] = 1.f;

    #pragma unroll
    for (int i = 0; i < 4; i++) {
        float phi = __ldg(qw + i * 3 + 0), th = __ldg(qw + i * 3 + 1), om = __ldg(qw + i * 3 + 2);
        float sh, ch; __sincosf(0.5f * th, &sh, &ch);
        float a = 0.5f * (phi + om), d = 0.5f * (phi - om);
        float sa, ca, sd, cd;
        __sincosf(a, &sa, &ca);
        __sincosf(d, &sd, &cd);
        float u00r =  ch * ca, u00i = -ch * sa;
        float u01r = -sh * cd, u01i = -sh * sd;
        float u10r =  sh * cd, u10i = -sh * sd;
        float u11r =  ch * ca, u11i =  ch * sa;
        const int s = 8 >> i;
        #pragma unroll
        for (int j = 0; j < 16; j++) {
            if ((j & s) == 0) {
                const int j1 = j | s;
                float ar = sr[j],  ai = si[j];
                float br = sr[j1], bi = si[j1];
                sr[j]  = u00r * ar - u00i * ai + u01r * br - u01i * bi;
                si[j]  = u00r * ai + u00i * ar + u01r * bi + u01i * br;
                sr[j1] = u10r * ar - u10i * ai + u11r * br - u11i * bi;
                si[j1] = u10r * ai + u10i * ar + u11r * bi + u11i * br;
            }
        }
    }
    #define SWP(A,B) { float t; t=sr[A]; sr[A]=sr[B]; sr[B]=t; t=si[A]; si[A]=si[B]; si[B]=t; }
    SWP(8,12) SWP(9,13) SWP(10,14) SWP(11,15)   // cnot(0,1)
    SWP(4,6)  SWP(5,7)  SWP(12,14) SWP(13,15)   // cnot(1,2)
    SWP(2,3)  SWP(6,7)  SWP(10,11) SWP(14,15)   // cnot(2,3)
    #undef SWP

    float Qv[4][4];
    #pragma unroll
    for (int q = 0; q < 4; q++)
        #pragma unroll
        for (int m = 0; m < 4; m++) Qv[q][m] = 0.f;
    #pragma unroll
    for (int j = 0; j < 16; j++) {
        #pragma unroll
        for (int m = 0; m < 4; m++) {
            float arm = __shfl_sync(0xffffffffu, sr[j], m);
            float aim = __shfl_sync(0xffffffffu, si[j], m);
            float p = sr[j] * arm + si[j] * aim;
            Qv[0][m] += (j & 8) ? -p : p;
            Qv[1][m] += (j & 4) ? -p : p;
            Qv[2][m] += (j & 2) ? -p : p;
            Qv[3][m] += (j & 1) ? -p : p;
        }
    }
    if (lane < 4) {
        #pragma unroll
        for (int q = 0; q < 4; q++)
            #pragma unroll
            for (int m = 0; m < 4; m++)
                g_Q[q][lane * 4 + m] = Qv[q][m];
    }
}

// ===================== Kernel 1: lean conv + quadratic form =====================
__global__ __launch_bounds__(EZTHR)
void ez_kernel(const float* __restrict__ x,
               const float* __restrict__ W_pre,
               const float* __restrict__ b_pre)
{
    __shared__ float x_s[C_IN][EZTILE + 2];     // 21.1 KB
    __shared__ float w_s[C_IN * 12];            // [c][k][q] 3.75 KB
    __shared__ float Q_s[4][16];
    __shared__ float bpre_s[4];

    const int tid = threadIdx.x;
    const int b   = blockIdx.y;
    const int l0  = blockIdx.x * EZTILE;

    // ---- staging (all threads) ----
    for (int i = tid; i < C_IN * 12; i += EZTHR) {
        int c = i / 12; int r = i - c * 12; int k = r >> 2; int q = r & 3;
        w_s[i] = W_pre[q * (C_IN * KW) + c * KW + k];
    }
    if (tid < 64) ((float*)Q_s)[tid] = ((const float*)g_Q)[tid];
    if (tid < 4)  bpre_s[tid] = b_pre[tid];

    const float* xb = x + (size_t)b * C_IN * L_IN;
    for (int i = tid; i < C_IN * (EZTILE + 2); i += EZTHR) {
        int c = i / (EZTILE + 2);
        int j = i - c * (EZTILE + 2);
        int l = l0 - 1 + j;
        x_s[c][j] = (l >= 0 && l < L_IN) ? xb[c * L_IN + l] : 0.0f;
    }
    __syncthreads();

    // ---- quad-split conv + shfl reduce ----
    const int pos = tid >> 2;                   // 0..63
    const int grp = tid & 3;                    // 0..3
    const int c0  = grp * C_PER_G;

    float v0 = 0.f, v1 = 0.f, v2 = 0.f, v3 = 0.f;
    #pragma unroll
    for (int ci = 0; ci < C_PER_G; ci++) {
        const int c = c0 + ci;
        float xa = x_s[c][pos], xb1 = x_s[c][pos + 1], xc = x_s[c][pos + 2];
        const float4* wr = (const float4*)&w_s[c * 12];
        float4 w0 = wr[0], w1 = wr[1], w2 = wr[2];
        v0 += w0.x * xa + w1.x * xb1 + w2.x * xc;
        v1 += w0.y * xa + w1.y * xb1 + w2.y * xc;
        v2 += w0.z * xa + w1.z * xb1 + w2.z * xc;
        v3 += w0.w * xa + w1.w * xb1 + w2.w * xc;
    }
    v0 += __shfl_xor_sync(0xffffffffu, v0, 1);
    v1 += __shfl_xor_sync(0xffffffffu, v1, 1);
    v2 += __shfl_xor_sync(0xffffffffu, v2, 1);
    v3 += __shfl_xor_sync(0xffffffffu, v3, 1);
    v0 += __shfl_xor_sync(0xffffffffu, v0, 2);
    v1 += __shfl_xor_sync(0xffffffffu, v1, 2);
    v2 += __shfl_xor_sync(0xffffffffu, v2, 2);
    v3 += __shfl_xor_sync(0xffffffffu, v3, 2);

    v0 += bpre_s[0]; v1 += bpre_s[1]; v2 += bpre_s[2]; v3 += bpre_s[3];

    const int l = l0 + pos;
    if (l >= L_IN) return;

    const float inv = __frcp_rn(v0 * v0 + v1 * v1 + v2 * v2 + v3 * v3);
    const float* Qr = &Q_s[grp][0];
    float s;
    s  = v0 * (Qr[0]  * v0 + Qr[1]  * v1 + Qr[2]  * v2 + Qr[3]  * v3);
    s += v1 * (Qr[4]  * v0 + Qr[5]  * v1 + Qr[6]  * v2 + Qr[7]  * v3);
    s += v2 * (Qr[8]  * v0 + Qr[9]  * v1 + Qr[10] * v2 + Qr[11] * v3);
    s += v3 * (Qr[12] * v0 + Qr[13] * v1 + Qr[14] * v2 + Qr[15] * v3);

    g_ez[((size_t)b * L_IN + l) * 4 + grp] = s * inv;   // tid-consecutive -> coalesced
}

// ===================== Kernel 2: writer (round-4 measured-best config) =====================
// grid: (24 l-tiles, 32 b). block = 512 (16 warps). Each warp sweeps o = wrp..511 step 16.
__global__ __launch_bounds__(512)
void write_kernel(const float* __restrict__ W_post,
                  const float* __restrict__ b_post,
                  float* __restrict__ out)
{
    const int tid  = threadIdx.x;
    const int b    = blockIdx.y;
    const int l0   = blockIdx.x * WTILE;
    const int lane = tid & 31;
    const int wrp  = tid >> 5;                  // 0..15
    const int l4   = l0 + lane * 4;
    if (l4 >= L_IN) return;                     // L_IN % 4 == 0: no straddle

    const float4* ezp = (const float4*)&g_ez[((size_t)b * L_IN + l4) * 4];
    const float4 e0 = __ldg(ezp + 0);
    const float4 e1 = __ldg(ezp + 1);
    const float4 e2 = __ldg(ezp + 2);
    const float4 e3 = __ldg(ezp + 3);

    float* outb = out + (size_t)b * OUT_CH * L_IN;

    #pragma unroll 8
    for (int o = wrp; o < OUT_CH; o += 16) {
        const float4 wp = __ldg((const float4*)(W_post + o * 4));
        const float  bp = __ldg(b_post + o);
        float4 r;
        r.x = fmaf(wp.x, e0.x, fmaf(wp.y, e0.y, fmaf(wp.z, e0.z, fmaf(wp.w, e0.w, bp))));
        r.y = fmaf(wp.x, e1.x, fmaf(wp.y, e1.y, fmaf(wp.z, e1.z, fmaf(wp.w, e1.w, bp))));
        r.z = fmaf(wp.x, e2.x, fmaf(wp.y, e2.y, fmaf(wp.z, e2.z, fmaf(wp.w, e2.w, bp))));
        r.w = fmaf(wp.x, e3.x, fmaf(wp.y, e3.y, fmaf(wp.z, e3.z, fmaf(wp.w, e3.w, bp))));
        __stcs((float4*)(outb + (size_t)o * L_IN + l4), r);
    }
}

extern "C" void kernel_launch(void* const* d_in, const int* in_sizes, int n_in,
                              void* d_out, int out_size)
{
    const float* x      = (const float*)d_in[0];
    const float* W_pre  = (const float*)d_in[1];
    const float* b_pre  = (const float*)d_in[2];
    const float* W_post = (const float*)d_in[3];
    const float* b_post = (const float*)d_in[4];
    const float* qw     = (const float*)d_in[5];
    float* out = (float*)d_out;

    const int B = in_sizes[0] / (C_IN * L_IN);                  // 32
    const int ez_tiles = (L_IN + EZTILE - 1) / EZTILE;          // 47
    const int w_tiles  = (L_IN + WTILE - 1) / WTILE;            // 24

    setup_q<<<1, 32>>>(qw);

    dim3 g1(ez_tiles, B);
    ez_kernel<<<g1, EZTHR>>>(x, W_pre, b_pre);

    dim3 g2(w_tiles, B);
    write_kernel<<<g2, 512>>>(W_post, b_post, out);
}

// round 11
// speedup vs baseline: 1.1878x; 1.1239x over previous
#include <cuda_runtime.h>

// QuantumConv1d, 2-kernel pipeline.
//  K1 (ez): LDS-minimized conv: thread (pg,cg) does 8 positions x 10 interleaved
//      channels, weights loaded once per channel per thread (5.5x less smem traffic).
//      Warp0 folds the circuit into 4 quadratic forms Q_q while warps 1-3 stage x.
//      Butterfly shfl reduce lands position p==cg on thread tid==pos -> coalesced
//      float4 store of expz to g_ez (1.5MB, L2-resident).
//  K2 (writer): round-4 measured-best: 512 thr, grid(24,32), float4 __stcs,
//      196.6MB streaming stores (the roofline term).

#define C_IN     80
#define L_IN     3000
#define OUT_CH   512
#define KW       3
#define TILE_L   128
#define EZTHR    128
#define WTILE    128
#define B_MAX    32

__device__ float4 g_ez4[B_MAX * L_IN];     // expz per (b,l): float4 over qubits

// ===================== Kernel 1 =====================
__global__ __launch_bounds__(EZTHR)
void ez_kernel(const float* __restrict__ x,
               const float* __restrict__ W_pre,
               const float* __restrict__ b_pre,
               const float* __restrict__ qw)
{
    __shared__ float x_s[C_IN][132];        // j = l - l0, j in 0..128 used; 42.2 KB
    __shared__ float x_lh[C_IN];            // left halo l0-1
    __shared__ float w_s[C_IN * 12];        // [c][k][q] 3.75 KB
    __shared__ float Q_s[4][16];
    __shared__ float bpre_s[4];

    const int tid = threadIdx.x;
    const int b   = blockIdx.y;
    const int l0  = blockIdx.x * TILE_L;

    // ======== Phase 0: warp 0 folds Q; warps 1-3 stage x + weights ========
    if (tid < 32) {
        const int k = tid & 3;
        float sr[16], si[16];
        #pragma unroll
        for (int j = 0; j < 16; j++) { sr[j] = 0.f; si[j] = 0.f; }
        #pragma unroll
        for (int j = 0; j < 4; j++) if (j == k) sr[j] = 1.f;

        #pragma unroll
        for (int i = 0; i < 4; i++) {
            float phi = __ldg(qw + i * 3 + 0), th = __ldg(qw + i * 3 + 1), om = __ldg(qw + i * 3 + 2);
            float sh, ch; __sincosf(0.5f * th, &sh, &ch);
            float a = 0.5f * (phi + om), d = 0.5f * (phi - om);
            float sa, ca, sd, cd;
            __sincosf(a, &sa, &ca);
            __sincosf(d, &sd, &cd);
            float u00r =  ch * ca, u00i = -ch * sa;
            float u01r = -sh * cd, u01i = -sh * sd;
            float u10r =  sh * cd, u10i = -sh * sd;
            float u11r =  ch * ca, u11i =  ch * sa;
            const int s = 8 >> i;
            #pragma unroll
            for (int j = 0; j < 16; j++) {
                if ((j & s) == 0) {
                    const int j1 = j | s;
                    float ar = sr[j],  ai = si[j];
                    float br = sr[j1], bi = si[j1];
                    sr[j]  = u00r * ar - u00i * ai + u01r * br - u01i * bi;
                    si[j]  = u00r * ai + u00i * ar + u01r * bi + u01i * br;
                    sr[j1] = u10r * ar - u10i * ai + u11r * br - u11i * bi;
                    si[j1] = u10r * ai + u10i * ar + u11r * bi + u11i * br;
                }
            }
        }
        #define SWP(A,B) { float t; t=sr[A]; sr[A]=sr[B]; sr[B]=t; t=si[A]; si[A]=si[B]; si[B]=t; }
        SWP(8,12) SWP(9,13) SWP(10,14) SWP(11,15)
        SWP(4,6)  SWP(5,7)  SWP(12,14) SWP(13,15)
        SWP(2,3)  SWP(6,7)  SWP(10,11) SWP(14,15)
        #undef SWP

        float Qv[4][4];
        #pragma unroll
        for (int q = 0; q < 4; q++)
            #pragma unroll
            for (int m = 0; m < 4; m++) Qv[q][m] = 0.f;
        #pragma unroll
        for (int j = 0; j < 16; j++) {
            #pragma unroll
            for (int m = 0; m < 4; m++) {
                float arm = __shfl_sync(0xffffffffu, sr[j], m);
                float aim = __shfl_sync(0xffffffffu, si[j], m);
                float p = sr[j] * arm + si[j] * aim;
                Qv[0][m] += (j & 8) ? -p : p;
                Qv[1][m] += (j & 4) ? -p : p;
                Qv[2][m] += (j & 2) ? -p : p;
                Qv[3][m] += (j & 1) ? -p : p;
            }
        }
        if (tid < 4) {
            #pragma unroll
            for (int q = 0; q < 4; q++)
                #pragma unroll
                for (int m = 0; m < 4; m++)
                    Q_s[q][tid * 4 + m] = Qv[q][m];
        }
    } else {
        const int t = tid - 32;                     // 0..95
        for (int i = t; i < C_IN * 12; i += EZTHR - 32) {
            int c = i / 12; int r = i - c * 12; int k = r >> 2; int q = r & 3;
            w_s[i] = W_pre[q * (C_IN * KW) + c * KW + k];
        }
        if (t < 4) bpre_s[t] = b_pre[t];

        const float* xb = x + (size_t)b * C_IN * L_IN;
        // interior: 80 rows x 32 float4 (j = 0..127 <-> l = l0..l0+127)
        for (int i = t; i < C_IN * 32; i += EZTHR - 32) {
            int c  = i >> 5;
            int qq = i & 31;
            int l  = l0 + qq * 4;
            float4 vv;
            if (l + 3 < L_IN) {
                vv = *(const float4*)(xb + (size_t)c * L_IN + l);
            } else {
                vv.x = (l + 0 < L_IN) ? xb[(size_t)c * L_IN + l + 0] : 0.f;
                vv.y = (l + 1 < L_IN) ? xb[(size_t)c * L_IN + l + 1] : 0.f;
                vv.z = (l + 2 < L_IN) ? xb[(size_t)c * L_IN + l + 2] : 0.f;
                vv.w = (l + 3 < L_IN) ? xb[(size_t)c * L_IN + l + 3] : 0.f;
            }
            *(float4*)&x_s[c][qq * 4] = vv;
        }
        // halos
        for (int c = t; c < C_IN; c += EZTHR - 32) {
            int lr = l0 + 128;
            x_s[c][128] = (lr < L_IN) ? xb[(size_t)c * L_IN + lr] : 0.f;
            int ll = l0 - 1;
            x_lh[c] = (ll >= 0) ? xb[(size_t)c * L_IN + ll] : 0.f;
        }
    }
    __syncthreads();

    // ======== Phase 1: 8-position conv, weights amortized ========
    const int pg   = tid >> 3;                  // 0..15 position-group
    const int cg   = tid & 7;                   // 0..7 channel-group
    const int pos0 = pg * 8;

    float acc[8][4];
    #pragma unroll
    for (int p = 0; p < 8; p++)
        #pragma unroll
        for (int q = 0; q < 4; q++) acc[p][q] = 0.f;

    #pragma unroll
    for (int ci = 0; ci < 10; ci++) {
        const int c = cg + ci * 8;              // interleaved: c mod 8 == cg
        const float* xr = &x_s[c][0];

        float xlm1;                              // x at j = pos0-1
        if (pg > 0) xlm1 = xr[pos0 - 1];
        else        xlm1 = x_lh[c];
        float4 xq1 = *(const float4*)(xr + pos0);       // j pos0..pos0+3
        float4 xq2 = *(const float4*)(xr + pos0 + 4);   // j pos0+4..pos0+7
        float xlp8 = xr[pos0 + 8];                      // j pos0+8

        float xwin[10] = { xlm1, xq1.x, xq1.y, xq1.z, xq1.w,
                           xq2.x, xq2.y, xq2.z, xq2.w, xlp8 };

        const float4* wr = (const float4*)&w_s[c * 12];
        float4 w0 = wr[0], w1 = wr[1], w2 = wr[2];

        #pragma unroll
        for (int p = 0; p < 8; p++) {
            acc[p][0] += w0.x * xwin[p] + w1.x * xwin[p + 1] + w2.x * xwin[p + 2];
            acc[p][1] += w0.y * xwin[p] + w1.y * xwin[p + 1] + w2.y * xwin[p + 2];
            acc[p][2] += w0.z * xwin[p] + w1.z * xwin[p + 1] + w2.z * xwin[p + 2];
            acc[p][3] += w0.w * xwin[p] + w1.w * xwin[p + 1] + w2.w * xwin[p + 2];
        }
    }

    // ======== Phase 2: butterfly reduce over cg; lane ends owning p == cg ========
    float b4[4][4];
    {
        float rx[8][4];
        #pragma unroll
        for (int p = 0; p < 8; p++)
            #pragma unroll
            for (int q = 0; q < 4; q++)
                rx[p][q] = __shfl_xor_sync(0xffffffffu, acc[p][q], 1);
        if (cg & 1) {
            #pragma unroll
            for (int j = 0; j < 4; j++)
                #pragma unroll
                for (int q = 0; q < 4; q++) b4[j][q] = acc[2*j+1][q] + rx[2*j+1][q];
        } else {
            #pragma unroll
            for (int j = 0; j < 4; j++)
                #pragma unroll
                for (int q = 0; q < 4; q++) b4[j][q] = acc[2*j][q] + rx[2*j][q];
        }
    }
    float c2[2][4];
    {
        float rx[4][4];
        #pragma unroll
        for (int j = 0; j < 4; j++)
            #pragma unroll
            for (int q = 0; q < 4; q++)
                rx[j][q] = __shfl_xor_sync(0xffffffffu, b4[j][q], 2);
        if (cg & 2) {
            #pragma unroll
            for (int i = 0; i < 2; i++)
                #pragma unroll
                for (int q = 0; q < 4; q++) c2[i][q] = b4[2*i+1][q] + rx[2*i+1][q];
        } else {
            #pragma unroll
            for (int i = 0; i < 2; i++)
                #pragma unroll
                for (int q = 0; q < 4; q++) c2[i][q] = b4[2*i][q] + rx[2*i][q];
        }
    }
    float v0, v1, v2, v3;
    {
        float rx[2][4];
        #pragma unroll
        for (int i = 0; i < 2; i++)
            #pragma unroll
            for (int q = 0; q < 4; q++)
                rx[i][q] = __shfl_xor_sync(0xffffffffu, c2[i][q], 4);
        if (cg & 4) {
            v0 = c2[1][0] + rx[1][0]; v1 = c2[1][1] + rx[1][1];
            v2 = c2[1][2] + rx[1][2]; v3 = c2[1][3] + rx[1][3];
        } else {
            v0 = c2[0][0] + rx[0][0]; v1 = c2[0][1] + rx[0][1];
            v2 = c2[0][2] + rx[0][2]; v3 = c2[0][3] + rx[0][3];
        }
    }
    // thread tid owns position pos = pos0 + cg == tid
    v0 += bpre_s[0]; v1 += bpre_s[1]; v2 += bpre_s[2]; v3 += bpre_s[3];

    const int l = l0 + tid;
    if (l >= L_IN) return;

    const float inv = __frcp_rn(v0 * v0 + v1 * v1 + v2 * v2 + v3 * v3);
    float e[4];
    #pragma unroll
    for (int q = 0; q < 4; q++) {
        const float* Qr = &Q_s[q][0];
        float s;
        s  = v0 * (Qr[0]  * v0 + Qr[1]  * v1 + Qr[2]  * v2 + Qr[3]  * v3);
        s += v1 * (Qr[4]  * v0 + Qr[5]  * v1 + Qr[6]  * v2 + Qr[7]  * v3);
        s += v2 * (Qr[8]  * v0 + Qr[9]  * v1 + Qr[10] * v2 + Qr[11] * v3);
        s += v3 * (Qr[12] * v0 + Qr[13] * v1 + Qr[14] * v2 + Qr[15] * v3);
        e[q] = s * inv;
    }
    g_ez4[(size_t)b * L_IN + l] = make_float4(e[0], e[1], e[2], e[3]);   // coalesced
}

// ===================== Kernel 2: writer (round-4 measured-best, unchanged) =====================
__global__ __launch_bounds__(512)
void write_kernel(const float* __restrict__ W_post,
                  const float* __restrict__ b_post,
                  float* __restrict__ out)
{
    const int tid  = threadIdx.x;
    const int b    = blockIdx.y;
    const int l0   = blockIdx.x * WTILE;
    const int lane = tid & 31;
    const int wrp  = tid >> 5;                  // 0..15
    const int l4   = l0 + lane * 4;
    if (l4 >= L_IN) return;                     // L_IN % 4 == 0: no straddle

    const float4* ezp = &g_ez4[(size_t)b * L_IN + l4];
    const float4 e0 = __ldg(ezp + 0);
    const float4 e1 = __ldg(ezp + 1);
    const float4 e2 = __ldg(ezp + 2);
    const float4 e3 = __ldg(ezp + 3);

    float* outb = out + (size_t)b * OUT_CH * L_IN;

    #pragma unroll 8
    for (int o = wrp; o < OUT_CH; o += 16) {
        const float4 wp = __ldg((const float4*)(W_post + o * 4));
        const float  bp = __ldg(b_post + o);
        float4 r;
        r.x = fmaf(wp.x, e0.x, fmaf(wp.y, e0.y, fmaf(wp.z, e0.z, fmaf(wp.w, e0.w, bp))));
        r.y = fmaf(wp.x, e1.x, fmaf(wp.y, e1.y, fmaf(wp.z, e1.z, fmaf(wp.w, e1.w, bp))));
        r.z = fmaf(wp.x, e2.x, fmaf(wp.y, e2.y, fmaf(wp.z, e2.z, fmaf(wp.w, e2.w, bp))));
        r.w = fmaf(wp.x, e3.x, fmaf(wp.y, e3.y, fmaf(wp.z, e3.z, fmaf(wp.w, e3.w, bp))));
        __stcs((float4*)(outb + (size_t)o * L_IN + l4), r);
    }
}

extern "C" void kernel_launch(void* const* d_in, const int* in_sizes, int n_in,
                              void* d_out, int out_size)
{
    const float* x      = (const float*)d_in[0];
    const float* W_pre  = (const float*)d_in[1];
    const float* b_pre  = (const float*)d_in[2];
    const float* W_post = (const float*)d_in[3];
    const float* b_post = (const float*)d_in[4];
    const float* qw     = (const float*)d_in[5];
    float* out = (float*)d_out;

    const int B = in_sizes[0] / (C_IN * L_IN);                  // 32
    const int n_tiles = (L_IN + TILE_L - 1) / TILE_L;           // 24

    dim3 g1(n_tiles, B);
    ez_kernel<<<g1, EZTHR>>>(x, W_pre, b_pre, qw);

    dim3 g2(n_tiles, B);
    write_kernel<<<g2, 512>>>(W_post, b_post, out);
}